// round 16
// baseline (speedup 1.0000x reference)
#include <cuda_runtime.h>
#include <cuda_bf16.h>
#include <math.h>
#include <stdint.h>

// ---------------- problem constants ----------------
#define NLAYERS 4
#define DMODEL  512
#define DINNER  1024
#define DSTATE  16
#define DTRANK  32
#define DCONV   4
#define BB      2
#define NCTX    768
#define NTGT    256
#define LSEQ    1024
#define NTOK    (BB * LSEQ)          // 2048
#define DBLW    (DTRANK + 2*DSTATE)  // 64
#define EPSV    1e-5f
#define NCHUNK  32
#define TCH     (LSEQ / NCHUNK)      // 32

#define WINE  (NLAYERS * DMODEL * 2 * DINNER)
#define WXE   (NLAYERS * DINNER * DBLW)
#define WOUTE (NLAYERS * DINNER * DMODEL)

// ---------------- scratch (device globals, no allocation) ----------------
__device__ float g_x[NTOK * DMODEL];
__device__ float g_xz[NTOK * 2 * DINNER];
__device__ float g_xc[NTOK * DINNER];
__device__ float g_dbl[NTOK * DBLW];
__device__ float g_dbl4[4 * NTOK * DBLW];
__device__ float g_delta[NTOK * DINNER];
__device__ float g_S[BB * NCHUNK * DINNER * DSTATE];
__device__ float g_P[BB * NCHUNK * DINNER * DSTATE];
__device__ float g_H[BB * NCHUNK * DINNER * DSTATE];
__device__ __align__(16) __nv_bfloat16 g_ub[NTOK * DMODEL];    // LN out
__device__ __align__(16) __nv_bfloat16 g_xcb[NTOK * DINNER];   // conv out
__device__ __align__(16) __nv_bfloat16 g_yb[NTOK * DINNER];    // scan out
__device__ __align__(16) __nv_bfloat16 g_Winb[WINE];
__device__ __align__(16) __nv_bfloat16 g_Wxb[WXE];
__device__ __align__(16) __nv_bfloat16 g_Woutb[WOUTE];

// ---------------- weight fp32 -> bf16 (one launch, all layers) -------------
__global__ void k_f2b(const float* __restrict__ w1, const float* __restrict__ w2,
                      const float* __restrict__ w3,
                      __nv_bfloat16* __restrict__ b1, __nv_bfloat16* __restrict__ b2,
                      __nv_bfloat16* __restrict__ b3) {
    const int N1 = WINE / 4, N2 = WXE / 4, N3 = WOUTE / 4;
    int i = blockIdx.x * blockDim.x + threadIdx.x;
    const float* src; __nv_bfloat16* dst; int j;
    if (i < N1)            { src = w1; dst = b1; j = i; }
    else if (i < N1 + N2)  { src = w2; dst = b2; j = i - N1; }
    else if (i < N1+N2+N3) { src = w3; dst = b3; j = i - N1 - N2; }
    else return;
    float4 v = reinterpret_cast<const float4*>(src)[j];
    __nv_bfloat162* d2 = reinterpret_cast<__nv_bfloat162*>(dst) + j * 2;
    d2[0] = __float22bfloat162_rn(make_float2(v.x, v.y));
    d2[1] = __float22bfloat162_rn(make_float2(v.z, v.w));
}

// ---------------- concat xc|xt -> residual stream ----------------
__global__ void k_concat(const float* __restrict__ xc, const float* __restrict__ xt,
                         float* __restrict__ x) {
    int i = blockIdx.x * blockDim.x + threadIdx.x;
    if (i >= NTOK * DMODEL) return;
    int d = i % DMODEL;
    int tok = i / DMODEL;
    int b = tok / LSEQ, l = tok % LSEQ;
    float v = (l < NCTX) ? xc[((size_t)(b * NCTX + l)) * DMODEL + d]
                         : xt[((size_t)(b * NTGT + (l - NCTX))) * DMODEL + d];
    x[i] = v;
}

// ---------------- layernorm -> bf16 output ----------------
__global__ void k_ln(const float* __restrict__ x, __nv_bfloat16* __restrict__ u,
                     const float* __restrict__ w, const float* __restrict__ b) {
    int tok = blockIdx.x;
    const float* xr = x + (size_t)tok * DMODEL;
    __nv_bfloat16* ur = u + (size_t)tok * DMODEL;
    int tid = threadIdx.x;

    float v0 = xr[tid], v1 = xr[tid + 256];

    __shared__ float red[8];
    __shared__ float bc[2];

    float s = v0 + v1;
    #pragma unroll
    for (int o = 16; o > 0; o >>= 1) s += __shfl_xor_sync(0xFFFFFFFFu, s, o);
    if ((tid & 31) == 0) red[tid >> 5] = s;
    __syncthreads();
    if (tid == 0) {
        float t = 0.f;
        #pragma unroll
        for (int i = 0; i < 8; i++) t += red[i];
        bc[0] = t * (1.0f / DMODEL);
    }
    __syncthreads();
    float mu = bc[0];

    float d0 = v0 - mu, d1 = v1 - mu;
    s = d0 * d0 + d1 * d1;
    #pragma unroll
    for (int o = 16; o > 0; o >>= 1) s += __shfl_xor_sync(0xFFFFFFFFu, s, o);
    if ((tid & 31) == 0) red[tid >> 5] = s;
    __syncthreads();
    if (tid == 0) {
        float t = 0.f;
        #pragma unroll
        for (int i = 0; i < 8; i++) t += red[i];
        bc[1] = t * (1.0f / DMODEL);
    }
    __syncthreads();
    float r = rsqrtf(bc[1] + EPSV);

    ur[tid]       = __float2bfloat16(d0 * r * w[tid]       + b[tid]);
    ur[tid + 256] = __float2bfloat16(d1 * r * w[tid + 256] + b[tid + 256]);
}

// ---------------- bf16 GEMM (mma.sync m16n8k16), plain LDG/LDS path -------
// C[M,N] (+)= A[M,K] @ B[K,N]; A,B bf16 row-major, C fp32.
// Same verified structure as the 627us kernel, but operands arrive bf16:
// A staged via 16B LDG (8 elems), B via paired scalar loads packed to words.
// Smem: k-contiguous rows, STRW=20 words (==4 mod 32 -> fragment bank
// = 4*g + t, injective over the warp). Split-K via gridDim.z.
template <int BM, int BN, int WM, int WN, bool ACC>
__global__ __launch_bounds__(WM * WN * 32)
void k_mma(int M, int N, int K,
           const __nv_bfloat16* __restrict__ A,
           const __nv_bfloat16* __restrict__ B,
           float* __restrict__ C) {
    constexpr int BK    = 32;
    constexpr int NTH   = WM * WN * 32;
    constexpr int STRW  = 20;                  // words per 32-elem row
    constexpr int MT    = BM / WM / 16;
    constexpr int NT    = BN / WN / 8;
    constexpr int APT   = (BM * 4) / NTH;      // 8-elem A chunks / thread
    constexpr int BPT   = (BK / 2) * BN / NTH; // packed B words / thread

    __shared__ uint32_t As[2][BM * STRW];
    __shared__ uint32_t Bs[2][BN * STRW];

    const int tid  = threadIdx.x;
    const int warp = tid >> 5;
    const int lane = tid & 31;
    const int wm   = warp / WN;
    const int wn   = warp % WN;
    const int g    = lane >> 2;
    const int t    = lane & 3;
    const int bm   = blockIdx.y * BM;
    const int bn   = blockIdx.x * BN;

    const int gz   = gridDim.z;
    const int kloc = K / gz;
    const int kb   = blockIdx.z * kloc;
    if (gz > 1) C += (size_t)blockIdx.z * M * N;

    float acc[MT][NT][4];
    #pragma unroll
    for (int i = 0; i < MT; i++)
        #pragma unroll
        for (int j = 0; j < NT; j++)
            #pragma unroll
            for (int c = 0; c < 4; c++) acc[i][j][c] = 0.f;

    auto load_tiles = [&](int k0, uint4* pa, uint32_t* pb) {
        #pragma unroll
        for (int i = 0; i < APT; i++) {
            int s = tid + i * NTH;
            int r = s >> 2, kc = (s & 3) * 8;
            pa[i] = *reinterpret_cast<const uint4*>(&A[(size_t)(bm + r) * K + k0 + kc]);
        }
        #pragma unroll
        for (int i = 0; i < BPT; i++) {
            int s = tid + i * NTH;
            int kp = s / BN, n = s % BN;
            uint16_t lo = *reinterpret_cast<const uint16_t*>(
                              &B[(size_t)(k0 + 2 * kp)     * N + bn + n]);
            uint16_t hi = *reinterpret_cast<const uint16_t*>(
                              &B[(size_t)(k0 + 2 * kp + 1) * N + bn + n]);
            pb[i] = (uint32_t)lo | ((uint32_t)hi << 16);
        }
    };
    auto store_tiles = [&](const uint4* pa, const uint32_t* pb,
                           uint32_t* as, uint32_t* bs) {
        #pragma unroll
        for (int i = 0; i < APT; i++) {
            int s = tid + i * NTH;
            int r = s >> 2, kw = (s & 3) * 4;
            uint32_t* dst = &as[r * STRW + kw];
            dst[0] = pa[i].x; dst[1] = pa[i].y;
            dst[2] = pa[i].z; dst[3] = pa[i].w;
        }
        #pragma unroll
        for (int i = 0; i < BPT; i++) {
            int s = tid + i * NTH;
            int kp = s / BN, n = s % BN;
            bs[n * STRW + kp] = pb[i];
        }
    };

    // prologue
    {
        uint4 pa[APT]; uint32_t pb[BPT];
        load_tiles(kb, pa, pb);
        store_tiles(pa, pb, As[0], Bs[0]);
    }
    __syncthreads();

    const int NIT = kloc / BK;
    for (int it = 0; it < NIT; it++) {
        const int s = it & 1;
        uint4 pa[APT]; uint32_t pb[BPT];
        const bool more = (it + 1) < NIT;
        if (more) load_tiles(kb + (it + 1) * BK, pa, pb);

        const uint32_t* as = As[s];
        const uint32_t* bs = Bs[s];
        #pragma unroll
        for (int k16 = 0; k16 < 2; k16++) {
            const int ko = k16 * 8;
            uint32_t af[MT][4];
            #pragma unroll
            for (int mi = 0; mi < MT; mi++) {
                int row = wm * (BM / WM) + mi * 16 + g;
                af[mi][0] = as[(row    ) * STRW + ko + t];
                af[mi][1] = as[(row + 8) * STRW + ko + t];
                af[mi][2] = as[(row    ) * STRW + ko + t + 4];
                af[mi][3] = as[(row + 8) * STRW + ko + t + 4];
            }
            uint32_t bf[NT][2];
            #pragma unroll
            for (int ni = 0; ni < NT; ni++) {
                int col = wn * (BN / WN) + ni * 8 + g;
                bf[ni][0] = bs[col * STRW + ko + t];
                bf[ni][1] = bs[col * STRW + ko + t + 4];
            }
            #pragma unroll
            for (int mi = 0; mi < MT; mi++)
                #pragma unroll
                for (int ni = 0; ni < NT; ni++) {
                    asm volatile(
                        "mma.sync.aligned.m16n8k16.row.col.f32.bf16.bf16.f32 "
                        "{%0,%1,%2,%3}, {%4,%5,%6,%7}, {%8,%9}, {%0,%1,%2,%3};"
                        : "+f"(acc[mi][ni][0]), "+f"(acc[mi][ni][1]),
                          "+f"(acc[mi][ni][2]), "+f"(acc[mi][ni][3])
                        : "r"(af[mi][0]), "r"(af[mi][1]), "r"(af[mi][2]), "r"(af[mi][3]),
                          "r"(bf[ni][0]), "r"(bf[ni][1]));
                }
        }
        if (more) store_tiles(pa, pb, As[s ^ 1], Bs[s ^ 1]);
        __syncthreads();
    }

    #pragma unroll
    for (int mi = 0; mi < MT; mi++) {
        int row0 = bm + wm * (BM / WM) + mi * 16 + g;
        #pragma unroll
        for (int ni = 0; ni < NT; ni++) {
            int col = bn + wn * (BN / WN) + ni * 8 + 2 * t;
            float* c0 = &C[(size_t)row0 * N + col];
            float* c1 = &C[(size_t)(row0 + 8) * N + col];
            if (ACC) {
                c0[0] += acc[mi][ni][0]; c0[1] += acc[mi][ni][1];
                c1[0] += acc[mi][ni][2]; c1[1] += acc[mi][ni][3];
            } else {
                c0[0] = acc[mi][ni][0]; c0[1] = acc[mi][ni][1];
                c1[0] = acc[mi][ni][2]; c1[1] = acc[mi][ni][3];
            }
        }
    }
}

// ---------------- reduce 4 split-K partials ----------------
__global__ void k_red4(const float* __restrict__ src, float* __restrict__ dst) {
    int i = blockIdx.x * blockDim.x + threadIdx.x;
    if (i >= NTOK * DBLW) return;
    const int S = NTOK * DBLW;
    dst[i] = (src[i] + src[i + S]) + (src[i + 2 * S] + src[i + 3 * S]);
}

// ---------------- causal depthwise conv + SiLU (fp32 + bf16 outputs) -------
__global__ void k_conv(const float* __restrict__ xz, float* __restrict__ xc,
                       __nv_bfloat16* __restrict__ xcb,
                       const float* __restrict__ cw, const float* __restrict__ cb) {
    int i = blockIdx.x * blockDim.x + threadIdx.x;
    if (i >= NTOK * DINNER) return;
    int d = i % DINNER;
    int tok = i / DINNER;
    int b = tok / LSEQ, l = tok % LSEQ;
    float acc = cb[d];
    #pragma unroll
    for (int k = 0; k < DCONV; k++) {
        int ls = l - (DCONV - 1) + k;
        if (ls >= 0)
            acc += xz[((size_t)(b * LSEQ + ls)) * (2 * DINNER) + d] * cw[d * DCONV + k];
    }
    acc = acc / (1.f + expf(-acc));
    xc[i]  = acc;
    xcb[i] = __float2bfloat16(acc);
}

// ---------------- fused dt @ Wdt + b_dt, softplus ----------------
__global__ void k_delta(const float* __restrict__ dbl, float* __restrict__ delta,
                        const float* __restrict__ Wdt, const float* __restrict__ bdt) {
    int tok = blockIdx.x;
    __shared__ float dt[DTRANK];
    if (threadIdx.x < DTRANK) dt[threadIdx.x] = dbl[(size_t)tok * DBLW + threadIdx.x];
    __syncthreads();
    for (int d = threadIdx.x; d < DINNER; d += blockDim.x) {
        float acc = bdt[d];
        #pragma unroll
        for (int r = 0; r < DTRANK; r++) acc += dt[r] * Wdt[r * DINNER + d];
        delta[(size_t)tok * DINNER + d] = (acc > 20.f) ? acc : log1pf(expf(acc));
    }
}

// ---------------- chunked selective scan: thread-per-channel ----------------
__device__ __forceinline__ void ld16(const float4* q, float* v) {
    float4 a = q[0], b = q[1], c = q[2], d = q[3];
    v[0]=a.x; v[1]=a.y; v[2]=a.z; v[3]=a.w;
    v[4]=b.x; v[5]=b.y; v[6]=b.z; v[7]=b.w;
    v[8]=c.x; v[9]=c.y; v[10]=c.z; v[11]=c.w;
    v[12]=d.x; v[13]=d.y; v[14]=d.z; v[15]=d.w;
}

__global__ void k_scanA(const float* __restrict__ xc, const float* __restrict__ dbl,
                        const float* __restrict__ delta,
                        float* __restrict__ S, float* __restrict__ P,
                        const float* __restrict__ A_log) {
    __shared__ float4 bs[TCH][4];
    const int d  = blockIdx.x * 128 + threadIdx.x;
    const int c  = blockIdx.y, b = blockIdx.z;
    const int t0 = c * TCH;

    for (int s = threadIdx.x; s < TCH * 16; s += 128) {
        int i = s >> 4, j = s & 15;
        reinterpret_cast<float*>(&bs[i][0])[j] =
            dbl[(size_t)(b * LSEQ + t0 + i) * DBLW + DTRANK + j];
    }
    __syncthreads();

    float an[16]; bool pw = true;
    #pragma unroll
    for (int n = 0; n < 16; n++) {
        an[n] = -expf(A_log[d * DSTATE + n]);
        pw = pw && (fabsf(an[n] + (float)(n + 1)) <= 1e-3f);
    }

    const float* delb = delta + ((size_t)(b * LSEQ + t0)) * DINNER + d;
    const float* xb   = xc    + ((size_t)(b * LSEQ + t0)) * DINNER + d;

    float h[16];
    #pragma unroll
    for (int n = 0; n < 16; n++) h[n] = 0.f;
    float sumd = 0.f;

    if (pw) {
        #pragma unroll 4
        for (int t = 0; t < TCH; t++) {
            float dlt = delb[(size_t)t * DINNER];
            float xt  = xb[(size_t)t * DINNER];
            sumd += dlt;
            float e1 = expf(-dlt);
            float t1 = dlt * xt;
            float Bt[16]; ld16(&bs[t][0], Bt);
            float e = 1.f;
            #pragma unroll
            for (int n = 0; n < 16; n++) { e *= e1; h[n] = e * h[n] + t1 * Bt[n]; }
        }
    } else {
        for (int t = 0; t < TCH; t++) {
            float dlt = delb[(size_t)t * DINNER];
            float xt  = xb[(size_t)t * DINNER];
            sumd += dlt;
            float t1 = dlt * xt;
            float Bt[16]; ld16(&bs[t][0], Bt);
            #pragma unroll
            for (int n = 0; n < 16; n++)
                h[n] = expf(dlt * an[n]) * h[n] + t1 * Bt[n];
        }
    }

    size_t idx = ((size_t)((b * NCHUNK + c) * DINNER) + d) * DSTATE;
    float4* S4 = reinterpret_cast<float4*>(&S[idx]);
    S4[0] = make_float4(h[0], h[1], h[2], h[3]);
    S4[1] = make_float4(h[4], h[5], h[6], h[7]);
    S4[2] = make_float4(h[8], h[9], h[10], h[11]);
    S4[3] = make_float4(h[12], h[13], h[14], h[15]);
    float p[16];
    #pragma unroll
    for (int n = 0; n < 16; n++) p[n] = expf(an[n] * sumd);
    float4* P4 = reinterpret_cast<float4*>(&P[idx]);
    P4[0] = make_float4(p[0], p[1], p[2], p[3]);
    P4[1] = make_float4(p[4], p[5], p[6], p[7]);
    P4[2] = make_float4(p[8], p[9], p[10], p[11]);
    P4[3] = make_float4(p[12], p[13], p[14], p[15]);
}

__global__ void k_scanB(const float* __restrict__ S, const float* __restrict__ P,
                        float* __restrict__ H) {
    int i = blockIdx.x * blockDim.x + threadIdx.x;
    if (i >= BB * DINNER * DSTATE) return;
    int b  = i / (DINNER * DSTATE);
    int dn = i % (DINNER * DSTATE);
    float h = 0.f;
    #pragma unroll
    for (int c = 0; c < NCHUNK; c++) {
        size_t idx = (size_t)(b * NCHUNK + c) * DINNER * DSTATE + dn;
        H[idx] = h;
        h = P[idx] * h + S[idx];
    }
}

__global__ void k_scanC(const float* __restrict__ xz, const float* __restrict__ xc,
                        const float* __restrict__ dbl, const float* __restrict__ delta,
                        const float* __restrict__ H, __nv_bfloat16* __restrict__ y,
                        const float* __restrict__ A_log, const float* __restrict__ Dvec) {
    __shared__ float4 bs[TCH][4];
    __shared__ float4 cs[TCH][4];
    const int d  = blockIdx.x * 128 + threadIdx.x;
    const int c  = blockIdx.y, b = blockIdx.z;
    const int t0 = c * TCH;

    for (int s = threadIdx.x; s < TCH * 32; s += 128) {
        int i = s >> 5, j = s & 31;
        float v = dbl[(size_t)(b * LSEQ + t0 + i) * DBLW + DTRANK + j];
        if (j < 16) reinterpret_cast<float*>(&bs[i][0])[j] = v;
        else        reinterpret_cast<float*>(&cs[i][0])[j - 16] = v;
    }
    __syncthreads();

    float an[16]; bool pw = true;
    #pragma unroll
    for (int n = 0; n < 16; n++) {
        an[n] = -expf(A_log[d * DSTATE + n]);
        pw = pw && (fabsf(an[n] + (float)(n + 1)) <= 1e-3f);
    }
    float Dd = Dvec[d];

    const float* delb = delta + ((size_t)(b * LSEQ + t0)) * DINNER + d;
    const float* xb   = xc    + ((size_t)(b * LSEQ + t0)) * DINNER + d;
    const float* zb   = xz    + ((size_t)(b * LSEQ + t0)) * (2 * DINNER) + DINNER + d;
    __nv_bfloat16* yb = y     + ((size_t)(b * LSEQ + t0)) * DINNER + d;

    float h[16];
    {
        size_t idx = ((size_t)((b * NCHUNK + c) * DINNER) + d) * DSTATE;
        ld16(reinterpret_cast<const float4*>(&H[idx]), h);
    }

    if (pw) {
        #pragma unroll 4
        for (int t = 0; t < TCH; t++) {
            float dlt = delb[(size_t)t * DINNER];
            float xt  = xb[(size_t)t * DINNER];
            float zt  = zb[(size_t)t * (2 * DINNER)];
            float e1  = expf(-dlt);
            float t1  = dlt * xt;
            float Bt[16], Ct[16];
            ld16(&bs[t][0], Bt);
            ld16(&cs[t][0], Ct);
            float e = 1.f, acc0 = 0.f, acc1 = 0.f;
            #pragma unroll
            for (int n = 0; n < 16; n += 2) {
                e *= e1; h[n]     = e * h[n]     + t1 * Bt[n];
                acc0 += h[n] * Ct[n];
                e *= e1; h[n + 1] = e * h[n + 1] + t1 * Bt[n + 1];
                acc1 += h[n + 1] * Ct[n + 1];
            }
            float yv = (acc0 + acc1) + xt * Dd;
            yv *= zt / (1.f + expf(-zt));
            yb[(size_t)t * DINNER] = __float2bfloat16(yv);
        }
    } else {
        for (int t = 0; t < TCH; t++) {
            float dlt = delb[(size_t)t * DINNER];
            float xt  = xb[(size_t)t * DINNER];
            float zt  = zb[(size_t)t * (2 * DINNER)];
            float t1  = dlt * xt;
            float Bt[16], Ct[16];
            ld16(&bs[t][0], Bt);
            ld16(&cs[t][0], Ct);
            float acc = 0.f;
            #pragma unroll
            for (int n = 0; n < 16; n++) {
                h[n] = expf(dlt * an[n]) * h[n] + t1 * Bt[n];
                acc += h[n] * Ct[n];
            }
            float yv = acc + xt * Dd;
            yv *= zt / (1.f + expf(-zt));
            yb[(size_t)t * DINNER] = __float2bfloat16(yv);
        }
    }
}

// ---------------- slice x[:, NCTX:, :] into output ----------------
__global__ void k_slice(const float* __restrict__ x, float* __restrict__ out) {
    int i = blockIdx.x * blockDim.x + threadIdx.x;
    if (i >= BB * NTGT * DMODEL) return;
    int d = i % DMODEL;
    int tok = i / DMODEL;
    int b = tok / NTGT, t = tok % NTGT;
    out[i] = x[((size_t)(b * LSEQ + NCTX + t)) * DMODEL + d];
}

// ---------------- launch ----------------
extern "C" void kernel_launch(void* const* d_in, const int* in_sizes, int n_in,
                              void* d_out, int out_size) {
    const float* xc    = (const float*)d_in[0];
    const float* xt    = (const float*)d_in[1];
    const float* Win   = (const float*)d_in[2];
    const float* convw = (const float*)d_in[3];
    const float* convb = (const float*)d_in[4];
    const float* Wx    = (const float*)d_in[5];
    const float* Wdt   = (const float*)d_in[6];
    const float* bdt   = (const float*)d_in[7];
    const float* Alog  = (const float*)d_in[8];
    const float* Dvec  = (const float*)d_in[9];
    const float* Wout  = (const float*)d_in[10];
    const float* lnw   = (const float*)d_in[11];
    const float* lnb   = (const float*)d_in[12];
    float* out = (float*)d_out;

    float *px, *pxz, *pxc, *pdbl, *pdbl4, *pdelta, *pS, *pP, *pH;
    __nv_bfloat16 *pub, *pxcb, *pyb, *pWinb, *pWxb, *pWoutb;
    cudaGetSymbolAddress((void**)&px,     g_x);
    cudaGetSymbolAddress((void**)&pxz,    g_xz);
    cudaGetSymbolAddress((void**)&pxc,    g_xc);
    cudaGetSymbolAddress((void**)&pdbl,   g_dbl);
    cudaGetSymbolAddress((void**)&pdbl4,  g_dbl4);
    cudaGetSymbolAddress((void**)&pdelta, g_delta);
    cudaGetSymbolAddress((void**)&pS,     g_S);
    cudaGetSymbolAddress((void**)&pP,     g_P);
    cudaGetSymbolAddress((void**)&pH,     g_H);
    cudaGetSymbolAddress((void**)&pub,    g_ub);
    cudaGetSymbolAddress((void**)&pxcb,   g_xcb);
    cudaGetSymbolAddress((void**)&pyb,    g_yb);
    cudaGetSymbolAddress((void**)&pWinb,  g_Winb);
    cudaGetSymbolAddress((void**)&pWxb,   g_Wxb);
    cudaGetSymbolAddress((void**)&pWoutb, g_Woutb);

    // 1) weights -> bf16 (all layers, one launch)
    {
        int nf4 = (WINE + WXE + WOUTE) / 4;
        k_f2b<<<(nf4 + 255) / 256, 256>>>(Win, Wx, Wout, pWinb, pWxb, pWoutb);
    }

    // 2) concat
    k_concat<<<(NTOK * DMODEL + 255) / 256, 256>>>(xc, xt, px);

    for (int l = 0; l < NLAYERS; l++) {
        const __nv_bfloat16* Winb_l  = pWinb  + (size_t)l * DMODEL * 2 * DINNER;
        const __nv_bfloat16* Wxb_l   = pWxb   + (size_t)l * DINNER * DBLW;
        const __nv_bfloat16* Woutb_l = pWoutb + (size_t)l * DINNER * DMODEL;
        const float* convw_l = convw + (size_t)l * DINNER * DCONV;
        const float* convb_l = convb + (size_t)l * DINNER;
        const float* Wdt_l   = Wdt   + (size_t)l * DTRANK * DINNER;
        const float* bdt_l   = bdt   + (size_t)l * DINNER;
        const float* Alog_l  = Alog  + (size_t)l * DINNER * DSTATE;
        const float* Dvec_l  = Dvec  + (size_t)l * DINNER;
        const float* lnw_l   = lnw   + (size_t)l * DMODEL;
        const float* lnb_l   = lnb   + (size_t)l * DMODEL;

        // layernorm -> bf16
        k_ln<<<NTOK, 256>>>(px, pub, lnw_l, lnb_l);

        // GEMM1: xz = u @ Win  (2048x512)@(512x2048)
        {
            dim3 grid((2 * DINNER) / 64, NTOK / 128);
            k_mma<128, 64, 4, 2, false><<<grid, 256>>>(NTOK, 2 * DINNER, DMODEL,
                                                       pub, Winb_l, pxz);
        }

        // conv + silu (fp32 + bf16)
        k_conv<<<(NTOK * DINNER + 255) / 256, 256>>>(pxz, pxc, pxcb, convw_l, convb_l);

        // GEMM2: dbl = xc @ Wx  (2048x1024)@(1024x64), split-K=4
        {
            dim3 grid(DBLW / 64, NTOK / 64, 4);
            k_mma<64, 64, 4, 1, false><<<grid, 128>>>(NTOK, DBLW, DINNER,
                                                      pxcb, Wxb_l, pdbl4);
            k_red4<<<(NTOK * DBLW + 255) / 256, 256>>>(pdbl4, pdbl);
        }

        // delta
        k_delta<<<NTOK, 256>>>(pdbl, pdelta, Wdt_l, bdt_l);

        // chunked scan
        {
            dim3 gridS(DINNER / 128, NCHUNK, BB);
            k_scanA<<<gridS, 128>>>(pxc, pdbl, pdelta, pS, pP, Alog_l);
            k_scanB<<<(BB * DINNER * DSTATE) / 256, 256>>>(pS, pP, pH);
            k_scanC<<<gridS, 128>>>(pxz, pxc, pdbl, pdelta, pH, pyb,
                                    Alog_l, Dvec_l);
        }

        // GEMM3: x += y @ Wout  (2048x1024)@(1024x512), accumulate
        {
            dim3 grid(DMODEL / 64, NTOK / 128);
            k_mma<128, 64, 4, 2, true><<<grid, 256>>>(NTOK, DMODEL, DINNER,
                                                      pyb, Woutb_l, px);
        }
    }

    k_slice<<<(BB * NTGT * DMODEL + 255) / 256, 256>>>(px, out);
}

// round 17
// speedup vs baseline: 1.0409x; 1.0409x over previous
#include <cuda_runtime.h>
#include <cuda_bf16.h>
#include <math.h>
#include <stdint.h>

// ---------------- problem constants ----------------
#define NLAYERS 4
#define DMODEL  512
#define DINNER  1024
#define DSTATE  16
#define DTRANK  32
#define DCONV   4
#define BB      2
#define NCTX    768
#define NTGT    256
#define LSEQ    1024
#define NTOK    (BB * LSEQ)          // 2048
#define DBLW    (DTRANK + 2*DSTATE)  // 64
#define EPSV    1e-5f
#define NCHUNK  32
#define TCH     (LSEQ / NCHUNK)      // 32

#define WINE  (NLAYERS * DMODEL * 2 * DINNER)
#define WXE   (NLAYERS * DINNER * DBLW)
#define WOUTE (NLAYERS * DINNER * DMODEL)

// ---------------- scratch (device globals, no allocation) ----------------
__device__ float g_x[NTOK * DMODEL];
__device__ float g_xz[NTOK * 2 * DINNER];
__device__ float g_xc[NTOK * DINNER];
__device__ float g_dbl[NTOK * DBLW];
__device__ float g_dbl4[4 * NTOK * DBLW];
__device__ float g_delta[NTOK * DINNER];
__device__ float g_S[BB * NCHUNK * DINNER * DSTATE];
__device__ float g_P[BB * NCHUNK * DINNER * DSTATE];
__device__ float g_H[BB * NCHUNK * DINNER * DSTATE];
__device__ __align__(16) __nv_bfloat16 g_ub[NTOK * DMODEL];
__device__ __align__(16) __nv_bfloat16 g_xcb[NTOK * DINNER];
__device__ __align__(16) __nv_bfloat16 g_yb[NTOK * DINNER];
__device__ __align__(16) __nv_bfloat16 g_Winb[WINE];
__device__ __align__(16) __nv_bfloat16 g_Wxb[WXE];
__device__ __align__(16) __nv_bfloat16 g_Woutb[WOUTE];

// ---------------- weight fp32 -> bf16 (one launch, all layers) -------------
__global__ void k_f2b(const float* __restrict__ w1, const float* __restrict__ w2,
                      const float* __restrict__ w3,
                      __nv_bfloat16* __restrict__ b1, __nv_bfloat16* __restrict__ b2,
                      __nv_bfloat16* __restrict__ b3) {
    const int N1 = WINE / 4, N2 = WXE / 4, N3 = WOUTE / 4;
    int i = blockIdx.x * blockDim.x + threadIdx.x;
    const float* src; __nv_bfloat16* dst; int j;
    if (i < N1)            { src = w1; dst = b1; j = i; }
    else if (i < N1 + N2)  { src = w2; dst = b2; j = i - N1; }
    else if (i < N1+N2+N3) { src = w3; dst = b3; j = i - N1 - N2; }
    else return;
    float4 v = reinterpret_cast<const float4*>(src)[j];
    __nv_bfloat162* d2 = reinterpret_cast<__nv_bfloat162*>(dst) + j * 2;
    d2[0] = __float22bfloat162_rn(make_float2(v.x, v.y));
    d2[1] = __float22bfloat162_rn(make_float2(v.z, v.w));
}

// ---------------- concat xc|xt -> residual stream ----------------
__global__ void k_concat(const float* __restrict__ xc, const float* __restrict__ xt,
                         float* __restrict__ x) {
    int i = blockIdx.x * blockDim.x + threadIdx.x;
    if (i >= NTOK * DMODEL) return;
    int d = i % DMODEL;
    int tok = i / DMODEL;
    int b = tok / LSEQ, l = tok % LSEQ;
    float v = (l < NCTX) ? xc[((size_t)(b * NCTX + l)) * DMODEL + d]
                         : xt[((size_t)(b * NTGT + (l - NCTX))) * DMODEL + d];
    x[i] = v;
}

// ---------------- layernorm -> bf16 output ----------------
__global__ void k_ln(const float* __restrict__ x, __nv_bfloat16* __restrict__ u,
                     const float* __restrict__ w, const float* __restrict__ b) {
    int tok = blockIdx.x;
    const float* xr = x + (size_t)tok * DMODEL;
    __nv_bfloat16* ur = u + (size_t)tok * DMODEL;
    int tid = threadIdx.x;

    float v0 = xr[tid], v1 = xr[tid + 256];

    __shared__ float red[8];
    __shared__ float bc[2];

    float s = v0 + v1;
    #pragma unroll
    for (int o = 16; o > 0; o >>= 1) s += __shfl_xor_sync(0xFFFFFFFFu, s, o);
    if ((tid & 31) == 0) red[tid >> 5] = s;
    __syncthreads();
    if (tid == 0) {
        float t = 0.f;
        #pragma unroll
        for (int i = 0; i < 8; i++) t += red[i];
        bc[0] = t * (1.0f / DMODEL);
    }
    __syncthreads();
    float mu = bc[0];

    float d0 = v0 - mu, d1 = v1 - mu;
    s = d0 * d0 + d1 * d1;
    #pragma unroll
    for (int o = 16; o > 0; o >>= 1) s += __shfl_xor_sync(0xFFFFFFFFu, s, o);
    if ((tid & 31) == 0) red[tid >> 5] = s;
    __syncthreads();
    if (tid == 0) {
        float t = 0.f;
        #pragma unroll
        for (int i = 0; i < 8; i++) t += red[i];
        bc[1] = t * (1.0f / DMODEL);
    }
    __syncthreads();
    float r = rsqrtf(bc[1] + EPSV);

    ur[tid]       = __float2bfloat16(d0 * r * w[tid]       + b[tid]);
    ur[tid + 256] = __float2bfloat16(d1 * r * w[tid + 256] + b[tid + 256]);
}

// ---------------- bf16 GEMM (mma.sync m16n8k16), plain LDG/LDS path -------
// C[M,N] (+)= A[M,K] @ B[K,N]; A,B bf16 row-major, C fp32.
// __launch_bounds__(NTH, 3): cap regs at 85 -> 3 CTAs/SM (was 86 -> 2 CTAs).
// B staged via 2x LDG.64 per (k-pair x 4n) unit, packed to k-pair words.
// Smem rows k-contiguous, STRW=20 (==4 mod 32 -> fragment bank 4g+t injective).
template <int BM, int BN, int WM, int WN, bool ACC>
__global__ __launch_bounds__(WM * WN * 32, 3)
void k_mma(int M, int N, int K,
           const __nv_bfloat16* __restrict__ A,
           const __nv_bfloat16* __restrict__ B,
           float* __restrict__ C) {
    constexpr int BK     = 32;
    constexpr int NTH    = WM * WN * 32;
    constexpr int STRW   = 20;
    constexpr int MT     = BM / WM / 16;
    constexpr int NT     = BN / WN / 8;
    constexpr int APT    = (BM * 4) / NTH;            // 8-elem A chunks / thread
    constexpr int BUNITS = (BK / 2) * (BN / 4);       // (k-pair x 4n) units
    constexpr int BUPT   = BUNITS / NTH;              // units / thread

    __shared__ uint32_t As[2][BM * STRW];
    __shared__ uint32_t Bs[2][BN * STRW];

    const int tid  = threadIdx.x;
    const int warp = tid >> 5;
    const int lane = tid & 31;
    const int wm   = warp / WN;
    const int wn   = warp % WN;
    const int g    = lane >> 2;
    const int t    = lane & 3;
    const int bm   = blockIdx.y * BM;
    const int bn   = blockIdx.x * BN;

    const int gz   = gridDim.z;
    const int kloc = K / gz;
    const int kb   = blockIdx.z * kloc;
    if (gz > 1) C += (size_t)blockIdx.z * M * N;

    float acc[MT][NT][4];
    #pragma unroll
    for (int i = 0; i < MT; i++)
        #pragma unroll
        for (int j = 0; j < NT; j++)
            #pragma unroll
            for (int c = 0; c < 4; c++) acc[i][j][c] = 0.f;

    auto load_tiles = [&](int k0, uint4* pa, uint32_t (*pb)[4]) {
        #pragma unroll
        for (int i = 0; i < APT; i++) {
            int s = tid + i * NTH;
            int r = s >> 2, kc = (s & 3) * 8;
            pa[i] = *reinterpret_cast<const uint4*>(&A[(size_t)(bm + r) * K + k0 + kc]);
        }
        #pragma unroll
        for (int i = 0; i < BUPT; i++) {
            int s = tid + i * NTH;
            int kp = s / (BN / 4), nc = s % (BN / 4);
            uint2 r0 = *reinterpret_cast<const uint2*>(
                           &B[(size_t)(k0 + 2 * kp)     * N + bn + nc * 4]);
            uint2 r1 = *reinterpret_cast<const uint2*>(
                           &B[(size_t)(k0 + 2 * kp + 1) * N + bn + nc * 4]);
            pb[i][0] = (r0.x & 0xFFFFu) | (r1.x << 16);
            pb[i][1] = (r0.x >> 16)     | (r1.x & 0xFFFF0000u);
            pb[i][2] = (r0.y & 0xFFFFu) | (r1.y << 16);
            pb[i][3] = (r0.y >> 16)     | (r1.y & 0xFFFF0000u);
        }
    };
    auto store_tiles = [&](const uint4* pa, const uint32_t (*pb)[4],
                           uint32_t* as, uint32_t* bs) {
        #pragma unroll
        for (int i = 0; i < APT; i++) {
            int s = tid + i * NTH;
            int r = s >> 2, kw = (s & 3) * 4;
            uint32_t* dst = &as[r * STRW + kw];
            dst[0] = pa[i].x; dst[1] = pa[i].y;
            dst[2] = pa[i].z; dst[3] = pa[i].w;
        }
        #pragma unroll
        for (int i = 0; i < BUPT; i++) {
            int s = tid + i * NTH;
            int kp = s / (BN / 4), nc = s % (BN / 4);
            #pragma unroll
            for (int j = 0; j < 4; j++)
                bs[(nc * 4 + j) * STRW + kp] = pb[i][j];
        }
    };

    // prologue
    {
        uint4 pa[APT]; uint32_t pb[BUPT][4];
        load_tiles(kb, pa, pb);
        store_tiles(pa, pb, As[0], Bs[0]);
    }
    __syncthreads();

    const int NIT = kloc / BK;
    for (int it = 0; it < NIT; it++) {
        const int s = it & 1;
        uint4 pa[APT]; uint32_t pb[BUPT][4];
        const bool more = (it + 1) < NIT;
        if (more) load_tiles(kb + (it + 1) * BK, pa, pb);

        const uint32_t* as = As[s];
        const uint32_t* bs = Bs[s];
        #pragma unroll
        for (int k16 = 0; k16 < 2; k16++) {
            const int ko = k16 * 8;
            uint32_t af[MT][4];
            #pragma unroll
            for (int mi = 0; mi < MT; mi++) {
                int row = wm * (BM / WM) + mi * 16 + g;
                af[mi][0] = as[(row    ) * STRW + ko + t];
                af[mi][1] = as[(row + 8) * STRW + ko + t];
                af[mi][2] = as[(row    ) * STRW + ko + t + 4];
                af[mi][3] = as[(row + 8) * STRW + ko + t + 4];
            }
            uint32_t bf[NT][2];
            #pragma unroll
            for (int ni = 0; ni < NT; ni++) {
                int col = wn * (BN / WN) + ni * 8 + g;
                bf[ni][0] = bs[col * STRW + ko + t];
                bf[ni][1] = bs[col * STRW + ko + t + 4];
            }
            #pragma unroll
            for (int mi = 0; mi < MT; mi++)
                #pragma unroll
                for (int ni = 0; ni < NT; ni++) {
                    asm volatile(
                        "mma.sync.aligned.m16n8k16.row.col.f32.bf16.bf16.f32 "
                        "{%0,%1,%2,%3}, {%4,%5,%6,%7}, {%8,%9}, {%0,%1,%2,%3};"
                        : "+f"(acc[mi][ni][0]), "+f"(acc[mi][ni][1]),
                          "+f"(acc[mi][ni][2]), "+f"(acc[mi][ni][3])
                        : "r"(af[mi][0]), "r"(af[mi][1]), "r"(af[mi][2]), "r"(af[mi][3]),
                          "r"(bf[ni][0]), "r"(bf[ni][1]));
                }
        }
        if (more) store_tiles(pa, pb, As[s ^ 1], Bs[s ^ 1]);
        __syncthreads();
    }

    #pragma unroll
    for (int mi = 0; mi < MT; mi++) {
        int row0 = bm + wm * (BM / WM) + mi * 16 + g;
        #pragma unroll
        for (int ni = 0; ni < NT; ni++) {
            int col = bn + wn * (BN / WN) + ni * 8 + 2 * t;
            float* c0 = &C[(size_t)row0 * N + col];
            float* c1 = &C[(size_t)(row0 + 8) * N + col];
            if (ACC) {
                c0[0] += acc[mi][ni][0]; c0[1] += acc[mi][ni][1];
                c1[0] += acc[mi][ni][2]; c1[1] += acc[mi][ni][3];
            } else {
                c0[0] = acc[mi][ni][0]; c0[1] = acc[mi][ni][1];
                c1[0] = acc[mi][ni][2]; c1[1] = acc[mi][ni][3];
            }
        }
    }
}

// ---------------- causal depthwise conv + SiLU, 4 channels/thread ----------
__global__ void k_conv(const float* __restrict__ xz, float* __restrict__ xc,
                       __nv_bfloat16* __restrict__ xcb,
                       const float* __restrict__ cw, const float* __restrict__ cb) {
    int i = blockIdx.x * blockDim.x + threadIdx.x;
    if (i >= NTOK * DINNER / 4) return;
    int d4  = (i % (DINNER / 4)) * 4;
    int tok = i / (DINNER / 4);
    int b = tok / LSEQ, l = tok % LSEQ;

    float4 w0 = *reinterpret_cast<const float4*>(&cw[(d4 + 0) * DCONV]);
    float4 w1 = *reinterpret_cast<const float4*>(&cw[(d4 + 1) * DCONV]);
    float4 w2 = *reinterpret_cast<const float4*>(&cw[(d4 + 2) * DCONV]);
    float4 w3 = *reinterpret_cast<const float4*>(&cw[(d4 + 3) * DCONV]);
    float4 a  = *reinterpret_cast<const float4*>(&cb[d4]);

    const float* wp0 = reinterpret_cast<const float*>(&w0);
    const float* wp1 = reinterpret_cast<const float*>(&w1);
    const float* wp2 = reinterpret_cast<const float*>(&w2);
    const float* wp3 = reinterpret_cast<const float*>(&w3);

    #pragma unroll
    for (int k = 0; k < DCONV; k++) {
        int ls = l - (DCONV - 1) + k;
        if (ls < 0) continue;
        float4 v = *reinterpret_cast<const float4*>(
                       &xz[((size_t)(b * LSEQ + ls)) * (2 * DINNER) + d4]);
        a.x += v.x * wp0[k];
        a.y += v.y * wp1[k];
        a.z += v.z * wp2[k];
        a.w += v.w * wp3[k];
    }
    a.x = a.x / (1.f + expf(-a.x));
    a.y = a.y / (1.f + expf(-a.y));
    a.z = a.z / (1.f + expf(-a.z));
    a.w = a.w / (1.f + expf(-a.w));

    size_t o = (size_t)tok * DINNER + d4;
    *reinterpret_cast<float4*>(&xc[o]) = a;
    __nv_bfloat162 p0 = __float22bfloat162_rn(make_float2(a.x, a.y));
    __nv_bfloat162 p1 = __float22bfloat162_rn(make_float2(a.z, a.w));
    uint2 pk; pk.x = *reinterpret_cast<uint32_t*>(&p0);
    pk.y = *reinterpret_cast<uint32_t*>(&p1);
    *reinterpret_cast<uint2*>(&xcb[o]) = pk;
}

// ---------------- fused: reduce 4 split-K partials + delta ----------------
__global__ void k_rd(const float* __restrict__ src4,
                     float* __restrict__ dbl, float* __restrict__ delta,
                     const float* __restrict__ Wdt, const float* __restrict__ bdt) {
    int tok = blockIdx.x;
    int tid = threadIdx.x;
    __shared__ float dt[DTRANK];

    if (tid < DBLW) {
        const int S = NTOK * DBLW;
        int j = tok * DBLW + tid;
        float v = (src4[j] + src4[j + S]) + (src4[j + 2 * S] + src4[j + 3 * S]);
        dbl[j] = v;
        if (tid < DTRANK) dt[tid] = v;
    }
    __syncthreads();

    for (int d = tid; d < DINNER; d += blockDim.x) {
        float acc = bdt[d];
        #pragma unroll
        for (int r = 0; r < DTRANK; r++) acc += dt[r] * Wdt[r * DINNER + d];
        delta[(size_t)tok * DINNER + d] = (acc > 20.f) ? acc : log1pf(expf(acc));
    }
}

// ---------------- chunked selective scan: thread-per-channel ----------------
__device__ __forceinline__ void ld16(const float4* q, float* v) {
    float4 a = q[0], b = q[1], c = q[2], d = q[3];
    v[0]=a.x; v[1]=a.y; v[2]=a.z; v[3]=a.w;
    v[4]=b.x; v[5]=b.y; v[6]=b.z; v[7]=b.w;
    v[8]=c.x; v[9]=c.y; v[10]=c.z; v[11]=c.w;
    v[12]=d.x; v[13]=d.y; v[14]=d.z; v[15]=d.w;
}

__global__ void k_scanA(const float* __restrict__ xc, const float* __restrict__ dbl,
                        const float* __restrict__ delta,
                        float* __restrict__ S, float* __restrict__ P,
                        const float* __restrict__ A_log) {
    __shared__ float4 bs[TCH][4];
    const int d  = blockIdx.x * 128 + threadIdx.x;
    const int c  = blockIdx.y, b = blockIdx.z;
    const int t0 = c * TCH;

    for (int s = threadIdx.x; s < TCH * 16; s += 128) {
        int i = s >> 4, j = s & 15;
        reinterpret_cast<float*>(&bs[i][0])[j] =
            dbl[(size_t)(b * LSEQ + t0 + i) * DBLW + DTRANK + j];
    }
    __syncthreads();

    float an[16]; bool pw = true;
    #pragma unroll
    for (int n = 0; n < 16; n++) {
        an[n] = -expf(A_log[d * DSTATE + n]);
        pw = pw && (fabsf(an[n] + (float)(n + 1)) <= 1e-3f);
    }

    const float* delb = delta + ((size_t)(b * LSEQ + t0)) * DINNER + d;
    const float* xb   = xc    + ((size_t)(b * LSEQ + t0)) * DINNER + d;

    float h[16];
    #pragma unroll
    for (int n = 0; n < 16; n++) h[n] = 0.f;
    float sumd = 0.f;

    if (pw) {
        #pragma unroll 4
        for (int t = 0; t < TCH; t++) {
            float dlt = delb[(size_t)t * DINNER];
            float xt  = xb[(size_t)t * DINNER];
            sumd += dlt;
            float e1 = expf(-dlt);
            float t1 = dlt * xt;
            float Bt[16]; ld16(&bs[t][0], Bt);
            float e = 1.f;
            #pragma unroll
            for (int n = 0; n < 16; n++) { e *= e1; h[n] = e * h[n] + t1 * Bt[n]; }
        }
    } else {
        for (int t = 0; t < TCH; t++) {
            float dlt = delb[(size_t)t * DINNER];
            float xt  = xb[(size_t)t * DINNER];
            sumd += dlt;
            float t1 = dlt * xt;
            float Bt[16]; ld16(&bs[t][0], Bt);
            #pragma unroll
            for (int n = 0; n < 16; n++)
                h[n] = expf(dlt * an[n]) * h[n] + t1 * Bt[n];
        }
    }

    size_t idx = ((size_t)((b * NCHUNK + c) * DINNER) + d) * DSTATE;
    float4* S4 = reinterpret_cast<float4*>(&S[idx]);
    S4[0] = make_float4(h[0], h[1], h[2], h[3]);
    S4[1] = make_float4(h[4], h[5], h[6], h[7]);
    S4[2] = make_float4(h[8], h[9], h[10], h[11]);
    S4[3] = make_float4(h[12], h[13], h[14], h[15]);
    float p[16];
    #pragma unroll
    for (int n = 0; n < 16; n++) p[n] = expf(an[n] * sumd);
    float4* P4 = reinterpret_cast<float4*>(&P[idx]);
    P4[0] = make_float4(p[0], p[1], p[2], p[3]);
    P4[1] = make_float4(p[4], p[5], p[6], p[7]);
    P4[2] = make_float4(p[8], p[9], p[10], p[11]);
    P4[3] = make_float4(p[12], p[13], p[14], p[15]);
}

__global__ void k_scanB(const float* __restrict__ S, const float* __restrict__ P,
                        float* __restrict__ H) {
    int i = blockIdx.x * blockDim.x + threadIdx.x;
    if (i >= BB * DINNER * DSTATE) return;
    int b  = i / (DINNER * DSTATE);
    int dn = i % (DINNER * DSTATE);
    float h = 0.f;
    #pragma unroll
    for (int c = 0; c < NCHUNK; c++) {
        size_t idx = (size_t)(b * NCHUNK + c) * DINNER * DSTATE + dn;
        H[idx] = h;
        h = P[idx] * h + S[idx];
    }
}

__global__ void k_scanC(const float* __restrict__ xz, const float* __restrict__ xc,
                        const float* __restrict__ dbl, const float* __restrict__ delta,
                        const float* __restrict__ H, __nv_bfloat16* __restrict__ y,
                        const float* __restrict__ A_log, const float* __restrict__ Dvec) {
    __shared__ float4 bs[TCH][4];
    __shared__ float4 cs[TCH][4];
    const int d  = blockIdx.x * 128 + threadIdx.x;
    const int c  = blockIdx.y, b = blockIdx.z;
    const int t0 = c * TCH;

    for (int s = threadIdx.x; s < TCH * 32; s += 128) {
        int i = s >> 5, j = s & 31;
        float v = dbl[(size_t)(b * LSEQ + t0 + i) * DBLW + DTRANK + j];
        if (j < 16) reinterpret_cast<float*>(&bs[i][0])[j] = v;
        else        reinterpret_cast<float*>(&cs[i][0])[j - 16] = v;
    }
    __syncthreads();

    float an[16]; bool pw = true;
    #pragma unroll
    for (int n = 0; n < 16; n++) {
        an[n] = -expf(A_log[d * DSTATE + n]);
        pw = pw && (fabsf(an[n] + (float)(n + 1)) <= 1e-3f);
    }
    float Dd = Dvec[d];

    const float* delb = delta + ((size_t)(b * LSEQ + t0)) * DINNER + d;
    const float* xb   = xc    + ((size_t)(b * LSEQ + t0)) * DINNER + d;
    const float* zb   = xz    + ((size_t)(b * LSEQ + t0)) * (2 * DINNER) + DINNER + d;
    __nv_bfloat16* yb = y     + ((size_t)(b * LSEQ + t0)) * DINNER + d;

    float h[16];
    {
        size_t idx = ((size_t)((b * NCHUNK + c) * DINNER) + d) * DSTATE;
        ld16(reinterpret_cast<const float4*>(&H[idx]), h);
    }

    if (pw) {
        #pragma unroll 4
        for (int t = 0; t < TCH; t++) {
            float dlt = delb[(size_t)t * DINNER];
            float xt  = xb[(size_t)t * DINNER];
            float zt  = zb[(size_t)t * (2 * DINNER)];
            float e1  = expf(-dlt);
            float t1  = dlt * xt;
            float Bt[16], Ct[16];
            ld16(&bs[t][0], Bt);
            ld16(&cs[t][0], Ct);
            float e = 1.f, acc0 = 0.f, acc1 = 0.f;
            #pragma unroll
            for (int n = 0; n < 16; n += 2) {
                e *= e1; h[n]     = e * h[n]     + t1 * Bt[n];
                acc0 += h[n] * Ct[n];
                e *= e1; h[n + 1] = e * h[n + 1] + t1 * Bt[n + 1];
                acc1 += h[n + 1] * Ct[n + 1];
            }
            float yv = (acc0 + acc1) + xt * Dd;
            yv *= zt / (1.f + expf(-zt));
            yb[(size_t)t * DINNER] = __float2bfloat16(yv);
        }
    } else {
        for (int t = 0; t < TCH; t++) {
            float dlt = delb[(size_t)t * DINNER];
            float xt  = xb[(size_t)t * DINNER];
            float zt  = zb[(size_t)t * (2 * DINNER)];
            float t1  = dlt * xt;
            float Bt[16], Ct[16];
            ld16(&bs[t][0], Bt);
            ld16(&cs[t][0], Ct);
            float acc = 0.f;
            #pragma unroll
            for (int n = 0; n < 16; n++) {
                h[n] = expf(dlt * an[n]) * h[n] + t1 * Bt[n];
                acc += h[n] * Ct[n];
            }
            float yv = acc + xt * Dd;
            yv *= zt / (1.f + expf(-zt));
            yb[(size_t)t * DINNER] = __float2bfloat16(yv);
        }
    }
}

// ---------------- slice x[:, NCTX:, :] into output ----------------
__global__ void k_slice(const float* __restrict__ x, float* __restrict__ out) {
    int i = blockIdx.x * blockDim.x + threadIdx.x;
    if (i >= BB * NTGT * DMODEL) return;
    int d = i % DMODEL;
    int tok = i / DMODEL;
    int b = tok / NTGT, t = tok % NTGT;
    out[i] = x[((size_t)(b * LSEQ + NCTX + t)) * DMODEL + d];
}

// ---------------- launch ----------------
extern "C" void kernel_launch(void* const* d_in, const int* in_sizes, int n_in,
                              void* d_out, int out_size) {
    const float* xc    = (const float*)d_in[0];
    const float* xt    = (const float*)d_in[1];
    const float* Win   = (const float*)d_in[2];
    const float* convw = (const float*)d_in[3];
    const float* convb = (const float*)d_in[4];
    const float* Wx    = (const float*)d_in[5];
    const float* Wdt   = (const float*)d_in[6];
    const float* bdt   = (const float*)d_in[7];
    const float* Alog  = (const float*)d_in[8];
    const float* Dvec  = (const float*)d_in[9];
    const float* Wout  = (const float*)d_in[10];
    const float* lnw   = (const float*)d_in[11];
    const float* lnb   = (const float*)d_in[12];
    float* out = (float*)d_out;

    float *px, *pxz, *pxc, *pdbl, *pdbl4, *pdelta, *pS, *pP, *pH;
    __nv_bfloat16 *pub, *pxcb, *pyb, *pWinb, *pWxb, *pWoutb;
    cudaGetSymbolAddress((void**)&px,     g_x);
    cudaGetSymbolAddress((void**)&pxz,    g_xz);
    cudaGetSymbolAddress((void**)&pxc,    g_xc);
    cudaGetSymbolAddress((void**)&pdbl,   g_dbl);
    cudaGetSymbolAddress((void**)&pdbl4,  g_dbl4);
    cudaGetSymbolAddress((void**)&pdelta, g_delta);
    cudaGetSymbolAddress((void**)&pS,     g_S);
    cudaGetSymbolAddress((void**)&pP,     g_P);
    cudaGetSymbolAddress((void**)&pH,     g_H);
    cudaGetSymbolAddress((void**)&pub,    g_ub);
    cudaGetSymbolAddress((void**)&pxcb,   g_xcb);
    cudaGetSymbolAddress((void**)&pyb,    g_yb);
    cudaGetSymbolAddress((void**)&pWinb,  g_Winb);
    cudaGetSymbolAddress((void**)&pWxb,   g_Wxb);
    cudaGetSymbolAddress((void**)&pWoutb, g_Woutb);

    // 1) weights -> bf16 (all layers, one launch)
    {
        int nf4 = (WINE + WXE + WOUTE) / 4;
        k_f2b<<<(nf4 + 255) / 256, 256>>>(Win, Wx, Wout, pWinb, pWxb, pWoutb);
    }

    // 2) concat
    k_concat<<<(NTOK * DMODEL + 255) / 256, 256>>>(xc, xt, px);

    for (int l = 0; l < NLAYERS; l++) {
        const __nv_bfloat16* Winb_l  = pWinb  + (size_t)l * DMODEL * 2 * DINNER;
        const __nv_bfloat16* Wxb_l   = pWxb   + (size_t)l * DINNER * DBLW;
        const __nv_bfloat16* Woutb_l = pWoutb + (size_t)l * DINNER * DMODEL;
        const float* convw_l = convw + (size_t)l * DINNER * DCONV;
        const float* convb_l = convb + (size_t)l * DINNER;
        const float* Wdt_l   = Wdt   + (size_t)l * DTRANK * DINNER;
        const float* bdt_l   = bdt   + (size_t)l * DINNER;
        const float* Alog_l  = Alog  + (size_t)l * DINNER * DSTATE;
        const float* Dvec_l  = Dvec  + (size_t)l * DINNER;
        const float* lnw_l   = lnw   + (size_t)l * DMODEL;
        const float* lnb_l   = lnb   + (size_t)l * DMODEL;

        // layernorm -> bf16
        k_ln<<<NTOK, 256>>>(px, pub, lnw_l, lnb_l);

        // GEMM1: xz = u @ Win  (2048x512)@(512x2048)
        {
            dim3 grid((2 * DINNER) / 64, NTOK / 128);
            k_mma<128, 64, 4, 2, false><<<grid, 256>>>(NTOK, 2 * DINNER, DMODEL,
                                                       pub, Winb_l, pxz);
        }

        // conv + silu (fp32 + bf16), 4 channels/thread
        k_conv<<<(NTOK * DINNER / 4 + 255) / 256, 256>>>(pxz, pxc, pxcb,
                                                         convw_l, convb_l);

        // GEMM2: dbl = xc @ Wx  (2048x1024)@(1024x64), split-K=4
        {
            dim3 grid(DBLW / 64, NTOK / 64, 4);
            k_mma<64, 64, 4, 1, false><<<grid, 128>>>(NTOK, DBLW, DINNER,
                                                      pxcb, Wxb_l, pdbl4);
        }

        // fused reduce + delta
        k_rd<<<NTOK, 256>>>(pdbl4, pdbl, pdelta, Wdt_l, bdt_l);

        // chunked scan
        {
            dim3 gridS(DINNER / 128, NCHUNK, BB);
            k_scanA<<<gridS, 128>>>(pxc, pdbl, pdelta, pS, pP, Alog_l);
            k_scanB<<<(BB * DINNER * DSTATE) / 256, 256>>>(pS, pP, pH);
            k_scanC<<<gridS, 128>>>(pxz, pxc, pdbl, pdelta, pH, pyb,
                                    Alog_l, Dvec_l);
        }

        // GEMM3: x += y @ Wout  (2048x1024)@(1024x512), accumulate
        {
            dim3 grid(DMODEL / 64, NTOK / 128);
            k_mma<128, 64, 4, 2, true><<<grid, 256>>>(NTOK, DMODEL, DINNER,
                                                      pyb, Woutb_l, px);
        }
    }

    k_slice<<<(BB * NTGT * DMODEL + 255) / 256, 256>>>(px, out);
}